// round 13
// baseline (speedup 1.0000x reference)
#include <cuda_runtime.h>
#include <cuda_bf16.h>
#include <math.h>
#include <stdint.h>

#define TPB 256   // 8 warps, 2 m16-tiles per warp = 256 batch elements per block

// ---- smem byte offsets ----
#define SO_BIAS 0         // 112 f32 (448 B)
#define SO_G32  512       // 16384 B: layer-0 staging (hi@0, lo@+8192), later g out
#define SO_LOA  16896     // lo-act frag buffer A: 8 warps x 7168 B = 57344
#define SO_LOB  74240     // lo-act frag buffer B: 57344
#define SO_WB   131584    // weights, max 50176 B
#define SMEM_BYTES 181760
#define STG_LO  8192u     // staging lo offset (256 rows x 32 B)
#define LO_WSTRIDE 7168u  // per-warp lo region (2 tiles x 7 kk x 512 B)
#define LO_T1   3584u     // tile-1 offset inside warp lo region

// ---- device-global weight image (prep output) ----
// per (layer, nt, kk, lane): uint4 {b0h, b1h, b0l, b1l}
__device__ __align__(16) uint4 g_wblob4[10368];
__device__ __align__(16) float g_biasblob[672];   // 6 x 112

// ---- PTX helpers ----
__device__ __forceinline__ uint32_t smem_u32(const void* p) {
    uint32_t a;
    asm("{ .reg .u64 t; cvta.to.shared.u64 t, %1; cvt.u32.u64 %0, t; }" : "=r"(a) : "l"(p));
    return a;
}
__device__ __forceinline__ uint32_t lds32(uint32_t a) {
    uint32_t v; asm volatile("ld.shared.b32 %0, [%1];" : "=r"(v) : "r"(a)); return v;
}
__device__ __forceinline__ uint4 lds128(uint32_t a) {
    uint4 v;
    asm volatile("ld.shared.v4.b32 {%0,%1,%2,%3}, [%4];"
                 : "=r"(v.x), "=r"(v.y), "=r"(v.z), "=r"(v.w) : "r"(a));
    return v;
}
__device__ __forceinline__ float2 ldsf2(uint32_t a) {
    float2 v; asm volatile("ld.shared.v2.f32 {%0,%1}, [%2];" : "=f"(v.x), "=f"(v.y) : "r"(a)); return v;
}
__device__ __forceinline__ void stsf2(uint32_t a, float x, float y) {
    asm volatile("st.shared.v2.f32 [%0], {%1,%2};" :: "r"(a), "f"(x), "f"(y) : "memory");
}
__device__ __forceinline__ void sts128(uint32_t a, uint32_t x, uint32_t y, uint32_t z, uint32_t w) {
    asm volatile("st.shared.v4.b32 [%0], {%1,%2,%3,%4};" :: "r"(a), "r"(x), "r"(y), "r"(z), "r"(w) : "memory");
}
__device__ __forceinline__ void hmma(float* c,
                                     const uint32_t* a,
                                     uint32_t b0, uint32_t b1) {
    asm volatile(
        "mma.sync.aligned.m16n8k16.row.col.f32.bf16.bf16.f32 "
        "{%0,%1,%2,%3}, {%4,%5,%6,%7}, {%8,%9}, {%0,%1,%2,%3};"
        : "+f"(c[0]), "+f"(c[1]), "+f"(c[2]), "+f"(c[3])
        : "r"(a[0]), "r"(a[1]), "r"(a[2]), "r"(a[3]), "r"(b0), "r"(b1));
}
__device__ __forceinline__ void hmma4(float* c,
                                      uint32_t a0, uint32_t a1, uint32_t a2, uint32_t a3,
                                      uint32_t b0, uint32_t b1) {
    asm volatile(
        "mma.sync.aligned.m16n8k16.row.col.f32.bf16.bf16.f32 "
        "{%0,%1,%2,%3}, {%4,%5,%6,%7}, {%8,%9}, {%0,%1,%2,%3};"
        : "+f"(c[0]), "+f"(c[1]), "+f"(c[2]), "+f"(c[3])
        : "r"(a0), "r"(a1), "r"(a2), "r"(a3), "r"(b0), "r"(b1));
}
__device__ __forceinline__ uint32_t pack_hi(float v0, float v1, float& r0, float& r1) {
    __nv_bfloat16 h0 = __float2bfloat16_rn(v0), h1 = __float2bfloat16_rn(v1);
    r0 = v0 - __bfloat162float(h0);
    r1 = v1 - __bfloat162float(h1);
    return (uint32_t)__bfloat16_as_ushort(h0) | ((uint32_t)__bfloat16_as_ushort(h1) << 16);
}
__device__ __forceinline__ uint32_t pack_lo(float r0, float r1) {
    __nv_bfloat16 l0 = __float2bfloat16_rn(r0), l1 = __float2bfloat16_rn(r1);
    return (uint32_t)__bfloat16_as_ushort(l0) | ((uint32_t)__bfloat16_as_ushort(l1) << 16);
}

// ---- 3x3 helpers ----
__device__ __forceinline__ void mm3(const float* a, const float* b, float* c) {
#pragma unroll
    for (int r = 0; r < 3; ++r)
#pragma unroll
        for (int k = 0; k < 3; ++k)
            c[r * 3 + k] = a[r * 3 + 0] * b[0 * 3 + k]
                         + a[r * 3 + 1] * b[1 * 3 + k]
                         + a[r * 3 + 2] * b[2 * 3 + k];
}
__device__ __forceinline__ float tr3(const float* a) { return a[0] + a[4] + a[8]; }
__device__ __forceinline__ float trAB(const float* a, const float* b) {
    float t = 0.f;
#pragma unroll
    for (int i = 0; i < 3; ++i)
#pragma unroll
        for (int k = 0; k < 3; ++k)
            t += a[i * 3 + k] * b[k * 3 + i];
    return t;
}
__device__ __forceinline__ void axpy9(float* acc, float g, const float* m) {
#pragma unroll
    for (int k = 0; k < 9; ++k) acc[k] += g * m[k];
}
__device__ __forceinline__ void axmy9(float* acc, float g, const float* m, const float* n) {
#pragma unroll
    for (int k = 0; k < 9; ++k) acc[k] += g * (m[k] - n[k]);
}

__device__ __forceinline__ void finish_elem(const float* __restrict__ Sg,
                                            const float* __restrict__ Wg,
                                            const float* g, long b, long bb,
                                            int Btot, float* __restrict__ out)
{
    float s[9], w[9];
#pragma unroll
    for (int k = 0; k < 9; ++k) { s[k] = Sg[bb * 9 + k]; w[k] = Wg[bb * 9 + k]; }
    float raw[9];
#pragma unroll
    for (int k = 0; k < 9; ++k) raw[k] = 0.f;

    axpy9(raw, g[0], s);
    float s2[9], w2[9];
    mm3(s, s, s2); mm3(w, w, w2);
    axpy9(raw, g[2], s2);
    { float c = g[2] * tr3(s2) * (1.f / 3.f); raw[0] -= c; raw[4] -= c; raw[8] -= c; }
    axpy9(raw, g[3], w2);
    { float c = g[3] * tr3(w2) * (1.f / 3.f); raw[0] -= c; raw[4] -= c; raw[8] -= c; }
    float sw[9], ws[9];
    mm3(s, w, sw); mm3(w, s, ws);
    axmy9(raw, g[1], sw, ws);
    float tA[9], tB[9];
    mm3(ws, w2, tA); mm3(w2, sw, tB); axmy9(raw, g[6], tA, tB);
    mm3(sw, s2, tA); mm3(s2, ws, tB); axmy9(raw, g[7], tA, tB);
    float ws2[9], s2w[9];
    mm3(w, s2, ws2); mm3(s2, w, s2w);
    axmy9(raw, g[4], ws2, s2w);
    mm3(ws2, w2, tA); mm3(w2, s2w, tB); axmy9(raw, g[9], tA, tB);
    mm3(w2, s, tA); mm3(s, w2, tB);
    axpy9(raw, g[5], tA); axpy9(raw, g[5], tB);
    { float c = g[5] * (2.f / 3.f) * tr3(tB); raw[0] -= c; raw[4] -= c; raw[8] -= c; }
    mm3(w2, s2, tA); mm3(s2, w2, tB);
    axpy9(raw, g[8], tA); axpy9(raw, g[8], tB);
    { float c = g[8] * (2.f / 3.f) * tr3(tB); raw[0] -= c; raw[4] -= c; raw[8] -= c; }

    float Q[9];
#pragma unroll
    for (int k = 0; k < 9; ++k) Q[k] = raw[k];
    { float c = (raw[0] + raw[4] + raw[8]) * (1.f / 3.f); Q[0] -= c; Q[4] -= c; Q[8] -= c; }
    float Qs[9];
#pragma unroll
    for (int r = 0; r < 3; ++r)
#pragma unroll
        for (int c = 0; c < 3; ++c)
            Qs[r * 3 + c] = 0.5f * (Q[r * 3 + c] + Q[c * 3 + r]);
    float ns = 0.f;
#pragma unroll
    for (int k = 0; k < 9; ++k) ns += Qs[k] * Qs[k];
    float invn = 1.0f / sqrtf(ns + 1e-16f);
    if (b < Btot) {
        float* outQ = out + b * 9;
        float* outR = out + (size_t)Btot * 9 + b * 9;
#pragma unroll
        for (int k = 0; k < 9; ++k) { outQ[k] = Qs[k] * invn; outR[k] = raw[k]; }
    }
}

// ================= prep kernel: W -> per-lane B-fragment blob ================
__global__ void prep_kernel(const float* W0, const float* W1, const float* W2,
                            const float* W3, const float* W4, const float* W5,
                            const float* B0, const float* B1, const float* B2,
                            const float* B3, const float* B4, const float* B5)
{
    const float* Ws[6] = {W0, W1, W2, W3, W4, W5};
    const float* Bs[6] = {B0, B1, B2, B3, B4, B5};
    const int Kt[6]  = {5, 50, 100, 100, 100, 50};
    const int Nt[6]  = {50, 100, 100, 100, 50, 10};
    const int KSt[6] = {1, 4, 7, 7, 7, 4};
    const int OFF[7] = {0, 256, 2048, 5184, 8320, 10112, 10368};

    int idx = blockIdx.x * blockDim.x + threadIdx.x;
    int stride = gridDim.x * blockDim.x;
    for (int i = idx; i < 10368; i += stride) {
        int l = 0;
#pragma unroll
        for (int q = 1; q < 6; ++q) if (i >= OFF[q]) l = q;
        int rem = i - OFF[l];
        int lane = rem & 31;
        int q2 = rem >> 5;
        int kk = q2 % KSt[l];
        int nt = q2 / KSt[l];
        int n = nt * 8 + (lane >> 2);
        int k0 = kk * 16 + 2 * (lane & 3);

        float f[4];
#pragma unroll
        for (int e = 0; e < 2; ++e) {
            int k = k0 + 8 * e;
            f[2 * e + 0] = (k < Kt[l] && n < Nt[l]) ? Ws[l][k * Nt[l] + n] : 0.f;
            f[2 * e + 1] = (k + 1 < Kt[l] && n < Nt[l]) ? Ws[l][(k + 1) * Nt[l] + n] : 0.f;
        }
        __nv_bfloat16 h[4], lo[4];
#pragma unroll
        for (int e = 0; e < 4; ++e) {
            h[e] = __float2bfloat16_rn(f[e]);
            lo[e] = __float2bfloat16_rn(f[e] - __bfloat162float(h[e]));
        }
        uint4 v;
        v.x = (uint32_t)__bfloat16_as_ushort(h[0]) | ((uint32_t)__bfloat16_as_ushort(h[1]) << 16);
        v.y = (uint32_t)__bfloat16_as_ushort(h[2]) | ((uint32_t)__bfloat16_as_ushort(h[3]) << 16);
        v.z = (uint32_t)__bfloat16_as_ushort(lo[0]) | ((uint32_t)__bfloat16_as_ushort(lo[1]) << 16);
        v.w = (uint32_t)__bfloat16_as_ushort(lo[2]) | ((uint32_t)__bfloat16_as_ushort(lo[3]) << 16);
        g_wblob4[i] = v;
    }
    for (int j = idx; j < 672; j += stride) {
        int l = j / 112, n = j - l * 112;
        g_biasblob[j] = (n < Nt[l]) ? Bs[l][n] : 0.f;
    }
}

// ===== one MLP layer: 2 m-tiles/warp, hi A-frags in regs, lo in smem =====
// KS k-steps, NT n-tiles (even). ah0/ah1 current hi frags (tile0/1);
// nh0/nh1 next hi frags; lo_rd/lo_wr warp-base lo buffers (tile1 at +LO_T1).
template <int KS, int NT, bool LAST>
__device__ __forceinline__ void layer_mma(
    uint32_t sb, int lane, int mbase,
    const uint32_t (*ah0)[4], const uint32_t (*ah1)[4],
    uint32_t (*nh0)[4], uint32_t (*nh1)[4],
    uint32_t lo_rd, uint32_t lo_wr)
{
    const uint32_t wb = sb + SO_WB + (uint32_t)lane * 16u;
    const uint32_t brow = sb + SO_BIAS;
    const uint32_t lrd = lo_rd + (uint32_t)lane * 16u;
    const uint32_t lwr = lo_wr + (uint32_t)lane * 16u;

#pragma unroll
    for (int nt = 0; nt < NT; nt += 2) {
        float c0[4] = {0.f, 0.f, 0.f, 0.f};
        float d0[4] = {0.f, 0.f, 0.f, 0.f};
        float c1[4] = {0.f, 0.f, 0.f, 0.f};
        float d1[4] = {0.f, 0.f, 0.f, 0.f};
        const uint32_t w0 = wb + (uint32_t)(nt * KS) * 512u;
        const uint32_t w1 = wb + (uint32_t)((nt + 1) * KS) * 512u;
#pragma unroll
        for (int kk = 0; kk < KS; ++kk) {
            uint4 wv0 = lds128(w0 + (uint32_t)kk * 512u);
            uint4 wv1 = lds128(w1 + (uint32_t)kk * 512u);
            uint4 av0 = lds128(lrd + (uint32_t)kk * 512u);
            uint4 av1 = lds128(lrd + LO_T1 + (uint32_t)kk * 512u);
            hmma(c0, ah0[kk], wv0.x, wv0.y);
            hmma(c1, ah1[kk], wv0.x, wv0.y);
            hmma(d0, ah0[kk], wv1.x, wv1.y);
            hmma(d1, ah1[kk], wv1.x, wv1.y);
            hmma(c0, ah0[kk], wv0.z, wv0.w);
            hmma(c1, ah1[kk], wv0.z, wv0.w);
            hmma(d0, ah0[kk], wv1.z, wv1.w);
            hmma(d1, ah1[kk], wv1.z, wv1.w);
            hmma4(c0, av0.x, av0.y, av0.z, av0.w, wv0.x, wv0.y);
            hmma4(c1, av1.x, av1.y, av1.z, av1.w, wv0.x, wv0.y);
            hmma4(d0, av0.x, av0.y, av0.z, av0.w, wv1.x, wv1.y);
            hmma4(d1, av1.x, av1.y, av1.z, av1.w, wv1.x, wv1.y);
        }
        const int col0 = nt * 8 + 2 * (lane & 3);
        float2 bp0 = ldsf2(brow + (uint32_t)col0 * 4u);
        float2 bp1 = ldsf2(brow + (uint32_t)(col0 + 8) * 4u);
#pragma unroll
        for (int t = 0; t < 2; ++t) {
            float* cc = t ? c1 : c0;
            float* dd = t ? d1 : d0;
            float v0 = cc[0] + bp0.x, v1 = cc[1] + bp0.y;
            float v2 = cc[2] + bp0.x, v3 = cc[3] + bp0.y;
            float u0 = dd[0] + bp1.x, u1 = dd[1] + bp1.y;
            float u2 = dd[2] + bp1.x, u3 = dd[3] + bp1.y;
            if (!LAST) {
                v0 = fmaxf(v0, 0.1f * v0); v1 = fmaxf(v1, 0.1f * v1);
                v2 = fmaxf(v2, 0.1f * v2); v3 = fmaxf(v3, 0.1f * v3);
                u0 = fmaxf(u0, 0.1f * u0); u1 = fmaxf(u1, 0.1f * u1);
                u2 = fmaxf(u2, 0.1f * u2); u3 = fmaxf(u3, 0.1f * u3);
                const int kk2 = nt >> 1;
                uint32_t (*nh)[4] = t ? nh1 : nh0;
                float r0, r1;
                uint32_t l0, l1, l2, l3;
                nh[kk2][0] = pack_hi(v0, v1, r0, r1); l0 = pack_lo(r0, r1);
                nh[kk2][1] = pack_hi(v2, v3, r0, r1); l1 = pack_lo(r0, r1);
                nh[kk2][2] = pack_hi(u0, u1, r0, r1); l2 = pack_lo(r0, r1);
                nh[kk2][3] = pack_hi(u2, u3, r0, r1); l3 = pack_lo(r0, r1);
                sts128(lwr + (t ? LO_T1 : 0u) + (uint32_t)kk2 * 512u, l0, l1, l2, l3);
            } else {
                const uint32_t grow = sb + SO_G32
                    + (uint32_t)(mbase + t * 16 + (lane >> 2)) * 64u;
                stsf2(grow + (uint32_t)col0 * 4u, v0, v1);
                stsf2(grow + 512u + (uint32_t)col0 * 4u, v2, v3);
                stsf2(grow + (uint32_t)(col0 + 8) * 4u, u0, u1);
                stsf2(grow + 512u + (uint32_t)(col0 + 8) * 4u, u2, u3);
            }
        }
    }
}

// ================= main kernel =================
__global__ void __launch_bounds__(TPB, 1) tbnn_hmma_kernel(
    const float* __restrict__ Sg, const float* __restrict__ Wg,
    float* __restrict__ out, int Btot)
{
    extern __shared__ char smemc[];
    const uint32_t sb = smem_u32(smemc);

    const int tid = threadIdx.x;
    const int lane = tid & 31;
    const int wid = tid >> 5;
    const int mbase = wid * 32;    // this warp's 32 rows (2 m16 tiles)
    const long blkbase = (long)blockIdx.x * 256;

    const uint32_t loA = sb + SO_LOA + (uint32_t)wid * LO_WSTRIDE;
    const uint32_t loB = sb + SO_LOB + (uint32_t)wid * LO_WSTRIDE;

    // ---- prologue: invariants -> staging rows (hi + lo), 32 B per row ----
    {
        const long b = blkbase + tid;
        const long bb = (b < Btot) ? b : (long)Btot - 1;
        float s[9], w[9];
#pragma unroll
        for (int k = 0; k < 9; ++k) { s[k] = Sg[bb * 9 + k]; w[k] = Wg[bb * 9 + k]; }
        float s2[9], w2[9];
        mm3(s, s, s2); mm3(w, w, w2);
        float inv[6];
        inv[0] = tr3(s2); inv[1] = tr3(w2); inv[2] = trAB(s2, s);
        inv[3] = trAB(w2, s); inv[4] = trAB(w2, s2); inv[5] = 0.f;

        uint32_t hw[8], lw[8];
#pragma unroll
        for (int j = 0; j < 8; ++j) { hw[j] = 0u; lw[j] = 0u; }
#pragma unroll
        for (int j = 0; j < 3; ++j) {
            float r0, r1;
            hw[j] = pack_hi(inv[2 * j], inv[2 * j + 1], r0, r1);
            lw[j] = pack_lo(r0, r1);
        }
        // second half rows: staging also covers rows tid+... no — one row per thread,
        // 256 threads cover all 256 rows.
        const uint32_t ra = sb + SO_G32 + (uint32_t)tid * 32u;
        sts128(ra, hw[0], hw[1], hw[2], hw[3]);
        sts128(ra + 16u, hw[4], hw[5], hw[6], hw[7]);
        sts128(ra + STG_LO, lw[0], lw[1], lw[2], lw[3]);
        sts128(ra + STG_LO + 16u, lw[4], lw[5], lw[6], lw[7]);
    }

    // ---- hi-fragment register files (ping-pong, 2 tiles) ----
    uint32_t ahA0[7][4], ahA1[7][4], ahB0[7][4], ahB1[7][4];

    const int N4[6]  = {256, 1792, 3136, 3136, 1792, 256};  // uint4 per layer
    const int OFF[6] = {0, 256, 2048, 5184, 8320, 10112};

#pragma unroll
    for (int l = 0; l < 6; ++l) {
        __syncthreads();   // prev layer wbuf reads done; prologue visible (l=0)
        {
            const uint4* src = g_wblob4 + OFF[l];
            uint4* dst = reinterpret_cast<uint4*>(smemc + SO_WB);
            const int n4 = N4[l];
            for (int i = tid; i < n4; i += TPB) dst[i] = src[i];
            float* bs = reinterpret_cast<float*>(smemc + SO_BIAS);
            for (int j = tid; j < 112; j += TPB) bs[j] = g_biasblob[l * 112 + j];
        }
        __syncthreads();

        if (l == 0) {
            // rows are 32 B apart; "row + 8" = +256 B; tile1 = +16 rows = +512 B
            const uint32_t aoff = sb + SO_G32 + (uint32_t)(mbase + (lane >> 2)) * 32u
                                + (uint32_t)(lane & 3) * 4u;
#pragma unroll
            for (int t = 0; t < 2; ++t) {
                const uint32_t ao = aoff + (uint32_t)t * 512u;
                uint32_t (*ah)[4] = t ? ahA1 : ahA0;
                ah[0][0] = lds32(ao);
                ah[0][1] = lds32(ao + 256u);
                ah[0][2] = lds32(ao + 16u);
                ah[0][3] = lds32(ao + 256u + 16u);
                uint32_t l0 = lds32(ao + STG_LO);
                uint32_t l1 = lds32(ao + STG_LO + 256u);
                uint32_t l2 = lds32(ao + STG_LO + 16u);
                uint32_t l3 = lds32(ao + STG_LO + 256u + 16u);
                sts128(loA + (t ? LO_T1 : 0u) + (uint32_t)lane * 16u, l0, l1, l2, l3);
            }
            __syncwarp();
            layer_mma<1, 8,  false>(sb, lane, mbase, ahA0, ahA1, ahB0, ahB1, loA, loB);
        }
        else if (l == 1) layer_mma<4, 14, false>(sb, lane, mbase, ahB0, ahB1, ahA0, ahA1, loB, loA);
        else if (l == 2) layer_mma<7, 14, false>(sb, lane, mbase, ahA0, ahA1, ahB0, ahB1, loA, loB);
        else if (l == 3) layer_mma<7, 14, false>(sb, lane, mbase, ahB0, ahB1, ahA0, ahA1, loB, loA);
        else if (l == 4) layer_mma<7, 8,  false>(sb, lane, mbase, ahA0, ahA1, ahB0, ahB1, loA, loB);
        else             layer_mma<4, 2,  true >(sb, lane, mbase, ahB0, ahB1, ahA0, ahA1, loB, loA);
    }
    __syncthreads();   // g32 visible

    // ---- epilogue: one element per thread ----
    {
        const long b = blkbase + tid;
        const long bb = (b < Btot) ? b : (long)Btot - 1;
        const float* gp = reinterpret_cast<const float*>(smemc + SO_G32) + tid * 16;
        float g[10];
#pragma unroll
        for (int n = 0; n < 10; ++n) g[n] = gp[n];
        finish_elem(Sg, Wg, g, b, bb, Btot, out);
    }
}

// ================= launch =================
extern "C" void kernel_launch(void* const* d_in, const int* in_sizes, int n_in,
                              void* d_out, int out_size)
{
    const float* s  = (const float*)d_in[0];
    const float* w  = (const float*)d_in[1];
    const float* W0 = (const float*)d_in[2];
    const float* B0 = (const float*)d_in[3];
    const float* W1 = (const float*)d_in[4];
    const float* B1 = (const float*)d_in[5];
    const float* W2 = (const float*)d_in[6];
    const float* B2 = (const float*)d_in[7];
    const float* W3 = (const float*)d_in[8];
    const float* B3 = (const float*)d_in[9];
    const float* W4 = (const float*)d_in[10];
    const float* B4 = (const float*)d_in[11];
    const float* W5 = (const float*)d_in[12];
    const float* B5 = (const float*)d_in[13];
    float* out = (float*)d_out;

    int Btot = in_sizes[0] / 9;

    prep_kernel<<<64, 256>>>(W0, W1, W2, W3, W4, W5, B0, B1, B2, B3, B4, B5);

    cudaFuncSetAttribute(tbnn_hmma_kernel,
                         cudaFuncAttributeMaxDynamicSharedMemorySize, SMEM_BYTES);
    int blocks = (Btot + 255) / 256;
    tbnn_hmma_kernel<<<blocks, TPB, SMEM_BYTES>>>(s, w, out, Btot);
}

// round 15
// speedup vs baseline: 1.2638x; 1.2638x over previous
#include <cuda_runtime.h>
#include <cuda_bf16.h>
#include <math.h>
#include <stdint.h>

#define TPB 512   // 16 warps, 256 batch elements per block

// ---- smem byte offsets ----
#define SO_BIAS 0          // 6 x 112 f32 = 2688 B (all layers, loaded once)
#define SO_LOA  2688       // lo-act frag buffer A: 16 warps x 3584 B = 57344
#define SO_LOB  60032      // lo-act frag buffer B: 57344
#define SO_WA   117376     // weight buffer A (even layers), 50176 B; g32 out overlaps base
#define SO_WB   167552     // weight buffer B (odd layers), 50176 B; layer-0 staging overlaps base
#define SMEM_BYTES 217728
#define STG_LO  8192u      // staging lo offset within WB (256 rows x 32 B hi, then lo)

// ---- device-global weight image (prep output) ----
// per (layer, nt, kk, lane): uint4 {b0h, b1h, b0l, b1l}
__device__ __align__(16) uint4 g_wblob4[10368];
__device__ __align__(16) float g_biasblob[672];   // 6 x 112

// ---- PTX helpers ----
__device__ __forceinline__ uint32_t smem_u32(const void* p) {
    uint32_t a;
    asm("{ .reg .u64 t; cvta.to.shared.u64 t, %1; cvt.u32.u64 %0, t; }" : "=r"(a) : "l"(p));
    return a;
}
__device__ __forceinline__ uint32_t lds32(uint32_t a) {
    uint32_t v; asm volatile("ld.shared.b32 %0, [%1];" : "=r"(v) : "r"(a)); return v;
}
__device__ __forceinline__ uint4 lds128(uint32_t a) {
    uint4 v;
    asm volatile("ld.shared.v4.b32 {%0,%1,%2,%3}, [%4];"
                 : "=r"(v.x), "=r"(v.y), "=r"(v.z), "=r"(v.w) : "r"(a));
    return v;
}
__device__ __forceinline__ float2 ldsf2(uint32_t a) {
    float2 v; asm volatile("ld.shared.v2.f32 {%0,%1}, [%2];" : "=f"(v.x), "=f"(v.y) : "r"(a)); return v;
}
__device__ __forceinline__ void stsf2(uint32_t a, float x, float y) {
    asm volatile("st.shared.v2.f32 [%0], {%1,%2};" :: "r"(a), "f"(x), "f"(y) : "memory");
}
__device__ __forceinline__ void sts128(uint32_t a, uint32_t x, uint32_t y, uint32_t z, uint32_t w) {
    asm volatile("st.shared.v4.b32 [%0], {%1,%2,%3,%4};" :: "r"(a), "r"(x), "r"(y), "r"(z), "r"(w) : "memory");
}
__device__ __forceinline__ void cpasync16(uint32_t dst, const void* src) {
    asm volatile("cp.async.cg.shared.global [%0], [%1], 16;"
                 :: "r"(dst), "l"(src) : "memory");
}
#define CP_COMMIT() asm volatile("cp.async.commit_group;" ::: "memory")
#define CP_WAIT0()  asm volatile("cp.async.wait_group 0;" ::: "memory")

__device__ __forceinline__ void prefetch_weights(uint32_t dst, const uint4* src,
                                                 int n4, int tid) {
    for (int i = tid; i < n4; i += TPB)
        cpasync16(dst + (uint32_t)i * 16u, src + i);
    CP_COMMIT();
}

__device__ __forceinline__ void hmma(float* c,
                                     const uint32_t* a,
                                     uint32_t b0, uint32_t b1) {
    asm volatile(
        "mma.sync.aligned.m16n8k16.row.col.f32.bf16.bf16.f32 "
        "{%0,%1,%2,%3}, {%4,%5,%6,%7}, {%8,%9}, {%0,%1,%2,%3};"
        : "+f"(c[0]), "+f"(c[1]), "+f"(c[2]), "+f"(c[3])
        : "r"(a[0]), "r"(a[1]), "r"(a[2]), "r"(a[3]), "r"(b0), "r"(b1));
}
__device__ __forceinline__ void hmma4(float* c,
                                      uint32_t a0, uint32_t a1, uint32_t a2, uint32_t a3,
                                      uint32_t b0, uint32_t b1) {
    asm volatile(
        "mma.sync.aligned.m16n8k16.row.col.f32.bf16.bf16.f32 "
        "{%0,%1,%2,%3}, {%4,%5,%6,%7}, {%8,%9}, {%0,%1,%2,%3};"
        : "+f"(c[0]), "+f"(c[1]), "+f"(c[2]), "+f"(c[3])
        : "r"(a0), "r"(a1), "r"(a2), "r"(a3), "r"(b0), "r"(b1));
}
__device__ __forceinline__ uint32_t pack_hi(float v0, float v1, float& r0, float& r1) {
    __nv_bfloat16 h0 = __float2bfloat16_rn(v0), h1 = __float2bfloat16_rn(v1);
    r0 = v0 - __bfloat162float(h0);
    r1 = v1 - __bfloat162float(h1);
    return (uint32_t)__bfloat16_as_ushort(h0) | ((uint32_t)__bfloat16_as_ushort(h1) << 16);
}
__device__ __forceinline__ uint32_t pack_lo(float r0, float r1) {
    __nv_bfloat16 l0 = __float2bfloat16_rn(r0), l1 = __float2bfloat16_rn(r1);
    return (uint32_t)__bfloat16_as_ushort(l0) | ((uint32_t)__bfloat16_as_ushort(l1) << 16);
}

// ---- 3x3 helpers ----
__device__ __forceinline__ void mm3(const float* a, const float* b, float* c) {
#pragma unroll
    for (int r = 0; r < 3; ++r)
#pragma unroll
        for (int k = 0; k < 3; ++k)
            c[r * 3 + k] = a[r * 3 + 0] * b[0 * 3 + k]
                         + a[r * 3 + 1] * b[1 * 3 + k]
                         + a[r * 3 + 2] * b[2 * 3 + k];
}
__device__ __forceinline__ float tr3(const float* a) { return a[0] + a[4] + a[8]; }
__device__ __forceinline__ float trAB(const float* a, const float* b) {
    float t = 0.f;
#pragma unroll
    for (int i = 0; i < 3; ++i)
#pragma unroll
        for (int k = 0; k < 3; ++k)
            t += a[i * 3 + k] * b[k * 3 + i];
    return t;
}
__device__ __forceinline__ void axpy9(float* acc, float g, const float* m) {
#pragma unroll
    for (int k = 0; k < 9; ++k) acc[k] += g * m[k];
}
__device__ __forceinline__ void axmy9(float* acc, float g, const float* m, const float* n) {
#pragma unroll
    for (int k = 0; k < 9; ++k) acc[k] += g * (m[k] - n[k]);
}

__device__ __forceinline__ void finish_elem(const float* __restrict__ Sg,
                                            const float* __restrict__ Wg,
                                            const float* g, long b, long bb,
                                            int Btot, float* __restrict__ out)
{
    float s[9], w[9];
#pragma unroll
    for (int k = 0; k < 9; ++k) { s[k] = Sg[bb * 9 + k]; w[k] = Wg[bb * 9 + k]; }
    float raw[9];
#pragma unroll
    for (int k = 0; k < 9; ++k) raw[k] = 0.f;

    axpy9(raw, g[0], s);
    float s2[9], w2[9];
    mm3(s, s, s2); mm3(w, w, w2);
    axpy9(raw, g[2], s2);
    { float c = g[2] * tr3(s2) * (1.f / 3.f); raw[0] -= c; raw[4] -= c; raw[8] -= c; }
    axpy9(raw, g[3], w2);
    { float c = g[3] * tr3(w2) * (1.f / 3.f); raw[0] -= c; raw[4] -= c; raw[8] -= c; }
    float sw[9], ws[9];
    mm3(s, w, sw); mm3(w, s, ws);
    axmy9(raw, g[1], sw, ws);
    float tA[9], tB[9];
    mm3(ws, w2, tA); mm3(w2, sw, tB); axmy9(raw, g[6], tA, tB);
    mm3(sw, s2, tA); mm3(s2, ws, tB); axmy9(raw, g[7], tA, tB);
    float ws2[9], s2w[9];
    mm3(w, s2, ws2); mm3(s2, w, s2w);
    axmy9(raw, g[4], ws2, s2w);
    mm3(ws2, w2, tA); mm3(w2, s2w, tB); axmy9(raw, g[9], tA, tB);
    mm3(w2, s, tA); mm3(s, w2, tB);
    axpy9(raw, g[5], tA); axpy9(raw, g[5], tB);
    { float c = g[5] * (2.f / 3.f) * tr3(tB); raw[0] -= c; raw[4] -= c; raw[8] -= c; }
    mm3(w2, s2, tA); mm3(s2, w2, tB);
    axpy9(raw, g[8], tA); axpy9(raw, g[8], tB);
    { float c = g[8] * (2.f / 3.f) * tr3(tB); raw[0] -= c; raw[4] -= c; raw[8] -= c; }

    float Q[9];
#pragma unroll
    for (int k = 0; k < 9; ++k) Q[k] = raw[k];
    { float c = (raw[0] + raw[4] + raw[8]) * (1.f / 3.f); Q[0] -= c; Q[4] -= c; Q[8] -= c; }
    float Qs[9];
#pragma unroll
    for (int r = 0; r < 3; ++r)
#pragma unroll
        for (int c = 0; c < 3; ++c)
            Qs[r * 3 + c] = 0.5f * (Q[r * 3 + c] + Q[c * 3 + r]);
    float ns = 0.f;
#pragma unroll
    for (int k = 0; k < 9; ++k) ns += Qs[k] * Qs[k];
    float invn = 1.0f / sqrtf(ns + 1e-16f);
    if (b < Btot) {
        float* outQ = out + b * 9;
        float* outR = out + (size_t)Btot * 9 + b * 9;
#pragma unroll
        for (int k = 0; k < 9; ++k) { outQ[k] = Qs[k] * invn; outR[k] = raw[k]; }
    }
}

// ================= prep kernel: W -> per-lane B-fragment blob ================
__global__ void prep_kernel(const float* W0, const float* W1, const float* W2,
                            const float* W3, const float* W4, const float* W5,
                            const float* B0, const float* B1, const float* B2,
                            const float* B3, const float* B4, const float* B5)
{
    const float* Ws[6] = {W0, W1, W2, W3, W4, W5};
    const float* Bs[6] = {B0, B1, B2, B3, B4, B5};
    const int Kt[6]  = {5, 50, 100, 100, 100, 50};
    const int Nt[6]  = {50, 100, 100, 100, 50, 10};
    const int KSt[6] = {1, 4, 7, 7, 7, 4};
    const int OFF[7] = {0, 256, 2048, 5184, 8320, 10112, 10368};

    int idx = blockIdx.x * blockDim.x + threadIdx.x;
    int stride = gridDim.x * blockDim.x;
    for (int i = idx; i < 10368; i += stride) {
        int l = 0;
#pragma unroll
        for (int q = 1; q < 6; ++q) if (i >= OFF[q]) l = q;
        int rem = i - OFF[l];
        int lane = rem & 31;
        int q2 = rem >> 5;
        int kk = q2 % KSt[l];
        int nt = q2 / KSt[l];
        int n = nt * 8 + (lane >> 2);
        int k0 = kk * 16 + 2 * (lane & 3);

        float f[4];
#pragma unroll
        for (int e = 0; e < 2; ++e) {
            int k = k0 + 8 * e;
            f[2 * e + 0] = (k < Kt[l] && n < Nt[l]) ? Ws[l][k * Nt[l] + n] : 0.f;
            f[2 * e + 1] = (k + 1 < Kt[l] && n < Nt[l]) ? Ws[l][(k + 1) * Nt[l] + n] : 0.f;
        }
        __nv_bfloat16 h[4], lo[4];
#pragma unroll
        for (int e = 0; e < 4; ++e) {
            h[e] = __float2bfloat16_rn(f[e]);
            lo[e] = __float2bfloat16_rn(f[e] - __bfloat162float(h[e]));
        }
        uint4 v;
        v.x = (uint32_t)__bfloat16_as_ushort(h[0]) | ((uint32_t)__bfloat16_as_ushort(h[1]) << 16);
        v.y = (uint32_t)__bfloat16_as_ushort(h[2]) | ((uint32_t)__bfloat16_as_ushort(h[3]) << 16);
        v.z = (uint32_t)__bfloat16_as_ushort(lo[0]) | ((uint32_t)__bfloat16_as_ushort(lo[1]) << 16);
        v.w = (uint32_t)__bfloat16_as_ushort(lo[2]) | ((uint32_t)__bfloat16_as_ushort(lo[3]) << 16);
        g_wblob4[i] = v;
    }
    for (int j = idx; j < 672; j += stride) {
        int l = j / 112, n = j - l * 112;
        g_biasblob[j] = (n < Nt[l]) ? Bs[l][n] : 0.f;
    }
}

// ===== one MLP layer: hi A-frags in regs, lo A-frags in warp-private smem ====
// wbase = this layer's weight buffer; brow = this layer's bias row.
template <int KS, int NT, bool LAST>
__device__ __forceinline__ void layer_mma(
    uint32_t sb, int lane, int mbase, uint32_t brow, uint32_t wbase,
    const uint32_t (*ah)[4], uint32_t (*nh)[4],
    uint32_t lo_rd, uint32_t lo_wr)
{
    const uint32_t wb = wbase + (uint32_t)lane * 16u;
    const uint32_t lrd = lo_rd + (uint32_t)lane * 16u;
    const uint32_t lwr = lo_wr + (uint32_t)lane * 16u;

#pragma unroll
    for (int nt = 0; nt < NT; nt += 2) {
        float c[4] = {0.f, 0.f, 0.f, 0.f};
        float d[4] = {0.f, 0.f, 0.f, 0.f};
        const uint32_t w0 = wb + (uint32_t)(nt * KS) * 512u;
        const uint32_t w1 = wb + (uint32_t)((nt + 1) * KS) * 512u;
#pragma unroll
        for (int kk = 0; kk < KS; ++kk) {
            uint4 wv0 = lds128(w0 + (uint32_t)kk * 512u);
            uint4 wv1 = lds128(w1 + (uint32_t)kk * 512u);
            uint4 av  = lds128(lrd + (uint32_t)kk * 512u);
            hmma(c, ah[kk], wv0.x, wv0.y);
            hmma(d, ah[kk], wv1.x, wv1.y);
            hmma(c, ah[kk], wv0.z, wv0.w);
            hmma(d, ah[kk], wv1.z, wv1.w);
            hmma4(c, av.x, av.y, av.z, av.w, wv0.x, wv0.y);
            hmma4(d, av.x, av.y, av.z, av.w, wv1.x, wv1.y);
        }
        const int col0 = nt * 8 + 2 * (lane & 3);
        float2 bp0 = ldsf2(brow + (uint32_t)col0 * 4u);
        float2 bp1 = ldsf2(brow + (uint32_t)(col0 + 8) * 4u);
        float v0 = c[0] + bp0.x, v1 = c[1] + bp0.y;
        float v2 = c[2] + bp0.x, v3 = c[3] + bp0.y;
        float u0 = d[0] + bp1.x, u1 = d[1] + bp1.y;
        float u2 = d[2] + bp1.x, u3 = d[3] + bp1.y;
        if (!LAST) {
            v0 = fmaxf(v0, 0.1f * v0); v1 = fmaxf(v1, 0.1f * v1);
            v2 = fmaxf(v2, 0.1f * v2); v3 = fmaxf(v3, 0.1f * v3);
            u0 = fmaxf(u0, 0.1f * u0); u1 = fmaxf(u1, 0.1f * u1);
            u2 = fmaxf(u2, 0.1f * u2); u3 = fmaxf(u3, 0.1f * u3);
            const int kk2 = nt >> 1;
            float r0, r1;
            uint32_t l0, l1, l2, l3;
            nh[kk2][0] = pack_hi(v0, v1, r0, r1); l0 = pack_lo(r0, r1);
            nh[kk2][1] = pack_hi(v2, v3, r0, r1); l1 = pack_lo(r0, r1);
            nh[kk2][2] = pack_hi(u0, u1, r0, r1); l2 = pack_lo(r0, r1);
            nh[kk2][3] = pack_hi(u2, u3, r0, r1); l3 = pack_lo(r0, r1);
            sts128(lwr + (uint32_t)kk2 * 512u, l0, l1, l2, l3);
        } else {
            // g output overlaps weight buffer A (dead at layer 5)
            const uint32_t grow = sb + SO_WA + (uint32_t)(mbase + (lane >> 2)) * 64u;
            stsf2(grow + (uint32_t)col0 * 4u, v0, v1);
            stsf2(grow + 512u + (uint32_t)col0 * 4u, v2, v3);
            stsf2(grow + (uint32_t)(col0 + 8) * 4u, u0, u1);
            stsf2(grow + 512u + (uint32_t)(col0 + 8) * 4u, u2, u3);
        }
    }
}

// ================= main kernel =================
__global__ void __launch_bounds__(TPB, 1) tbnn_hmma_kernel(
    const float* __restrict__ Sg, const float* __restrict__ Wg,
    float* __restrict__ out, int Btot)
{
    extern __shared__ char smemc[];
    const uint32_t sb = smem_u32(smemc);

    const int tid = threadIdx.x;
    const int lane = tid & 31;
    const int wid = tid >> 5;
    const int mbase = wid * 16;
    const long blkbase = (long)blockIdx.x * 256;

    const uint32_t loA = sb + SO_LOA + (uint32_t)wid * 3584u;
    const uint32_t loB = sb + SO_LOB + (uint32_t)wid * 3584u;

    // ---- prefetch layer-0 weights + all biases ----
    prefetch_weights(sb + SO_WA, g_wblob4, 256, tid);
    for (int i = tid; i < 168; i += TPB)
        cpasync16(sb + SO_BIAS + (uint32_t)i * 16u,
                  reinterpret_cast<const uint4*>(g_biasblob) + i);
    CP_COMMIT();

    // ---- prologue: invariants -> staging rows in WB (hi@0, lo@+8192) ----
    // ONE row per thread; only threads 0..255 own rows.
    if (tid < 256) {
        const long b = blkbase + tid;
        const long bb = (b < Btot) ? b : (long)Btot - 1;
        float s[9], w[9];
#pragma unroll
        for (int k = 0; k < 9; ++k) { s[k] = Sg[bb * 9 + k]; w[k] = Wg[bb * 9 + k]; }
        float s2[9], w2[9];
        mm3(s, s, s2); mm3(w, w, w2);
        float inv[6];
        inv[0] = tr3(s2); inv[1] = tr3(w2); inv[2] = trAB(s2, s);
        inv[3] = trAB(w2, s); inv[4] = trAB(w2, s2); inv[5] = 0.f;

        uint32_t hw[8], lw[8];
#pragma unroll
        for (int j = 0; j < 8; ++j) { hw[j] = 0u; lw[j] = 0u; }
#pragma unroll
        for (int j = 0; j < 3; ++j) {
            float r0, r1;
            hw[j] = pack_hi(inv[2 * j], inv[2 * j + 1], r0, r1);
            lw[j] = pack_lo(r0, r1);
        }
        const uint32_t ra = sb + SO_WB + (uint32_t)tid * 32u;
        sts128(ra, hw[0], hw[1], hw[2], hw[3]);
        sts128(ra + 16u, hw[4], hw[5], hw[6], hw[7]);
        sts128(ra + STG_LO, lw[0], lw[1], lw[2], lw[3]);
        sts128(ra + STG_LO + 16u, lw[4], lw[5], lw[6], lw[7]);
    }
    CP_WAIT0();
    __syncthreads();   // L0 weights + biases + all staging visible

    // ---- hi-fragment register files (ping-pong) ----
    uint32_t ahA[7][4], ahB[7][4];

    const int N4[6]  = {256, 1792, 3136, 3136, 1792, 256};
    const int OFF[6] = {0, 256, 2048, 5184, 8320, 10112};

#pragma unroll
    for (int l = 0; l < 6; ++l) {
        const uint32_t wcur = (l & 1) ? (sb + SO_WB) : (sb + SO_WA);
        const uint32_t wnext = (l & 1) ? (sb + SO_WA) : (sb + SO_WB);
        const uint32_t brow = sb + SO_BIAS + (uint32_t)l * 448u;

        if (l == 0) {
            // A-frags from WB staging; rows 32 B apart, "row+8" = +256 B
            const uint32_t aoff = sb + SO_WB + (uint32_t)(mbase + (lane >> 2)) * 32u
                                + (uint32_t)(lane & 3) * 4u;
            ahA[0][0] = lds32(aoff);
            ahA[0][1] = lds32(aoff + 256u);
            ahA[0][2] = lds32(aoff + 16u);
            ahA[0][3] = lds32(aoff + 256u + 16u);
            uint32_t l0 = lds32(aoff + STG_LO);
            uint32_t l1 = lds32(aoff + STG_LO + 256u);
            uint32_t l2 = lds32(aoff + STG_LO + 16u);
            uint32_t l3 = lds32(aoff + STG_LO + 256u + 16u);
            sts128(loA + (uint32_t)lane * 16u, l0, l1, l2, l3);
            __syncthreads();   // ALL warps consumed staging before WB overwrite
            prefetch_weights(sb + SO_WB, g_wblob4 + OFF[1], N4[1], tid);
            layer_mma<1, 8,  false>(sb, lane, mbase, brow, sb + SO_WA, ahA, ahB, loA, loB);
        } else {
            CP_WAIT0();
            __syncthreads();   // this layer's weights landed in all threads
            if (l < 5)
                prefetch_weights(wnext, g_wblob4 + OFF[l + 1], N4[l + 1], tid);
            if (l == 1)      layer_mma<4, 14, false>(sb, lane, mbase, brow, wcur, ahB, ahA, loB, loA);
            else if (l == 2) layer_mma<7, 14, false>(sb, lane, mbase, brow, wcur, ahA, ahB, loA, loB);
            else if (l == 3) layer_mma<7, 14, false>(sb, lane, mbase, brow, wcur, ahB, ahA, loB, loA);
            else if (l == 4) layer_mma<7, 8,  false>(sb, lane, mbase, brow, wcur, ahA, ahB, loA, loB);
            else             layer_mma<4, 2,  true >(sb, lane, mbase, brow, wcur, ahB, ahA, loB, loA);
        }
    }
    __syncthreads();   // g32 (in WA) visible

    // ---- epilogue: one element per thread; only threads 0..255 own elements ----
    if (tid < 256) {
        const long b = blkbase + tid;
        const long bb = (b < Btot) ? b : (long)Btot - 1;
        const float* gp = reinterpret_cast<const float*>(smemc + SO_WA) + tid * 16;
        float g[10];
#pragma unroll
        for (int n = 0; n < 10; ++n) g[n] = gp[n];
        finish_elem(Sg, Wg, g, b, bb, Btot, out);
    }
}

// ================= launch =================
extern "C" void kernel_launch(void* const* d_in, const int* in_sizes, int n_in,
                              void* d_out, int out_size)
{
    const float* s  = (const float*)d_in[0];
    const float* w  = (const float*)d_in[1];
    const float* W0 = (const float*)d_in[2];
    const float* B0 = (const float*)d_in[3];
    const float* W1 = (const float*)d_in[4];
    const float* B1 = (const float*)d_in[5];
    const float* W2 = (const float*)d_in[6];
    const float* B2 = (const float*)d_in[7];
    const float* W3 = (const float*)d_in[8];
    const float* B3 = (const float*)d_in[9];
    const float* W4 = (const float*)d_in[10];
    const float* B4 = (const float*)d_in[11];
    const float* W5 = (const float*)d_in[12];
    const float* B5 = (const float*)d_in[13];
    float* out = (float*)d_out;

    int Btot = in_sizes[0] / 9;

    prep_kernel<<<64, 256>>>(W0, W1, W2, W3, W4, W5, B0, B1, B2, B3, B4, B5);

    cudaFuncSetAttribute(tbnn_hmma_kernel,
                         cudaFuncAttributeMaxDynamicSharedMemorySize, SMEM_BYTES);
    int blocks = (Btot + 255) / 256;
    tbnn_hmma_kernel<<<blocks, TPB, SMEM_BYTES>>>(s, w, out, Btot);
}